// round 13
// baseline (speedup 1.0000x reference)
#include <cuda_runtime.h>
#include <cstdint>

#define TT 2048
#define CH 32
#define NCH (TT / CH)      // 64 chunks
#define PAD 33

__device__ __forceinline__ float ex2_ap (float x){ float r; asm("ex2.approx.f32 %0, %1;"   : "=f"(r) : "f"(x)); return r; }
__device__ __forceinline__ float rcp_ap (float x){ float r; asm("rcp.approx.f32 %0, %1;"   : "=f"(r) : "f"(x)); return r; }
__device__ __forceinline__ float sqrt_ap(float x){ float r; asm("sqrt.approx.f32 %0, %1;"  : "=f"(r) : "f"(x)); return r; }
__device__ __forceinline__ float rsq_ap (float x){ float r; asm("rsqrt.approx.f32 %0, %1;" : "=f"(r) : "f"(x)); return r; }
__device__ __forceinline__ float clampf(float x, float lo, float hi){ return fminf(fmaxf(x, lo), hi); }
__device__ __forceinline__ float relu(float x){ return fmaxf(x, 0.f); }

// dynamic smem layout (bytes)
#define SZ_P2   (2 * CH * PAD * 16)
#define SZ_P3A  (2 * CH * PAD * 16)
#define SZ_P0A  (2 * CH * PAD * 8)
#define SZ_P0B  (4 * CH * PAD * 8)
#define SZ_P1   (3 * CH * PAD * 8)
#define SZ_P3B  (2 * CH * PAD * 8)
#define OFF_P2   0
#define OFF_P3A  (OFF_P2  + SZ_P2)
#define OFF_P0A  (OFF_P3A + SZ_P3A)
#define OFF_P0B  (OFF_P0A + SZ_P0A)
#define OFF_P1   (OFF_P0B + SZ_P0B)
#define OFF_P3B  (OFF_P1  + SZ_P1)
#define OFF_FIN1 (OFF_P3B + SZ_P3B)
#define OFF_FIN2 (OFF_FIN1 + 128)
#define OFF_RS0  (OFF_FIN2 + 128)
#define SMEM_TOTAL (OFF_RS0 + 128)

struct Consts {
  float insc, Sc, Sinv, kexp, lCc, sub, crak, rk, lg, kr, ls;
};

// Full pass-2 Q for t==0: rolled SMS/GW = FINAL states, RS = outs[b,0,2]
__device__ __forceinline__ float q_final(float4 v, float SMS1r, float GW1r, float RSr, const Consts& c)
{
  float Prec = v.x, PET = v.y, RSmax = v.z, Area = v.w;
  float INTC = fminf(fminf(c.insc, PET), Prec);
  float INR  = Prec - INTC;
  float SMS1c = fmaxf(fminf(SMS1r, c.Sc), 0.f);
  float infil = ex2_ap(fmaf(c.kexp, SMS1c, c.lCc));
  float RMO = fminf(INR, infil);
  float IRUN = INR - RMO;
  float ratio = SMS1c * c.Sinv;
  float SRUN = c.sub * ratio * RMO;
  float BAS = c.rk * relu(GW1r);
  float inflow = (IRUN + SRUN + BAS) * Area;
  float x5 = RSr + inflow - RSmax;
  float Qor = relu(x5);
  float r = relu(RSr) * rcp_ap(RSmax);
  float pw = r * sqrt_ap(r);
  float Qir = (x5 > 0.f) ? (c.kr * RSmax) : (c.kr * RSr * pw);
  float drarg = (SRUN + IRUN) * (1.f - Area) + Qir + Qor - c.ls;
  float DR = relu(drarg);
  float GD = BAS * (1.f - Area);
  return relu(DR + GD);
}

__global__ void __launch_bounds__(160, 1)
hirnn_kernel(const float4* __restrict__ xin_all,
             const float* __restrict__ pINSC, const float* __restrict__ pCOEFF,
             const float* __restrict__ pSQ,   const float* __restrict__ pSMSC,
             const float* __restrict__ pSUB,  const float* __restrict__ pCRAK,
             const float* __restrict__ pRecK, const float* __restrict__ pKr,
             const float* __restrict__ pLG,   const float* __restrict__ pLS,
             float* __restrict__ out, int B)
{
  const int lane = threadIdx.x & 31;
  const int warp = threadIdx.x >> 5;
  const int seq  = blockIdx.x * 32 + lane;

  extern __shared__ unsigned char dyn[];
  typedef float2 P2CH[CH][PAD];
  typedef float4 P4CH[CH][PAD];
  P4CH* p2  = (P4CH*)(dyn + OFF_P2);    // [2]: BAS, crs, krR, RSov
  P4CH* p3a = (P4CH*)(dyn + OFF_P3A);   // [2]: x6, krR, qno, U
  P2CH* p0a = (P2CH*)(dyn + OFF_P0A);   // [2]: INR, POT
  P2CH* p0b = (P2CH*)(dyn + OFF_P0B);   // [4]: RSmax, Area
  P2CH* p1  = (P2CH*)(dyn + OFF_P1);    // [3]: U, RECn
  P2CH* p3b = (P2CH*)(dyn + OFF_P3B);   // [2]: BAS, onemA
  float* fin1 = (float*)(dyn + OFF_FIN1);
  float* fin2 = (float*)(dyn + OFF_FIN2);
  float* rs0s = (float*)(dyn + OFF_RS0);

  Consts c;
  c.insc = clampf(pINSC[0] * 5.f, 0.5f, 5.f);
  float Cc = clampf(pCOEFF[0] * 400.f, 50.f, 400.f);
  float qv = clampf(pSQ[0] * 6.f, 0.f, 6.f);
  c.Sc   = clampf(pSMSC[0] * 500.f, 50.f, 500.f);
  c.Sinv = 1.f / c.Sc;
  c.kexp = -qv * c.Sinv * 1.4426950408889634f;   // Cc*exp(-q*s/S) == exp2(kexp*s + lCc)
  c.lCc  = log2f(Cc);
  c.sub  = clampf(pSUB[0], 0.f, 1.f);
  c.crak = clampf(pCRAK[0], 0.f, 1.f);
  c.rk   = clampf(pRecK[0] * 0.3f, 0.003f, 0.3f);
  c.lg   = clampf(pLG[0] * 0.1f, 0.001f, 0.1f);
  c.kr   = clampf(pKr[0] * 0.1f, 0.01f, 0.1f);
  c.ls   = clampf(pLS[0] * 10.f, 0.01f, 10.f);

  const float4* __restrict__ xin = xin_all + (size_t)seq * TT;
  float* __restrict__ op = out + (size_t)seq * TT;

  if (warp == 0) {
    // ---------- stage 0: load + interception (streamed in groups of 8) ----------
    float4 gb[8];
#pragma unroll
    for (int i = 0; i < 8; i++) gb[i] = xin[i];
    for (int e = 0; e < NCH + 4; ++e) {
      if (e < NCH) {
        const int s1 = e & 1, s3 = e & 3;
#pragma unroll
        for (int gi = 0; gi < CH / 8; ++gi) {
          float4 cur[8];
#pragma unroll
          for (int i = 0; i < 8; i++) cur[i] = gb[i];
          const int nxt = e * CH + (gi + 1) * 8;
          if (nxt < TT) {
#pragma unroll
            for (int i = 0; i < 8; i++) gb[i] = xin[nxt + i];
          }
#pragma unroll
          for (int i = 0; i < 8; i++) {
            float Prec = cur[i].x, PET = cur[i].y;
            float INTC = fminf(fminf(c.insc, PET), Prec);
            p0a[s1][gi * 8 + i][lane] = make_float2(Prec - INTC, PET - INTC);
            p0b[s3][gi * 8 + i][lane] = make_float2(cur[i].z, cur[i].w);
          }
        }
      }
      __syncthreads();
    }
  } else if (warp == 1) {
    // ---------- stage 1: SMS recurrence ----------
    float S = 0.f;
    for (int e = 0; e < NCH + 4; ++e) {
      const int k = e - 1;
      if (k >= 0 && k < NCH) {
        const int s0 = k & 1, sd = k % 3;
#pragma unroll
        for (int i = 0; i < CH; i++) {
          float2 io = p0a[s0][i][lane];
          float INR = io.x, POT = io.y;
          float SMS1c = fminf(S, c.Sc);                 // >=0 invariant
          float infil = ex2_ap(fmaf(c.kexp, SMS1c, c.lCc));
          float ratio = SMS1c * c.Sinv;
          float sr  = c.sub  * ratio;
          float cr  = c.crak * ratio;
          float msr = 1.f - sr;
          float m   = msr * (1.f - cr);
          float mcr = cr * msr;
          float ETS  = fminf(POT, 10.f * ratio);
          float base = SMS1c - ETS;
          float w = fmaf(m, INR,   base);
          float z = fmaf(m, infil, base);
          float SMSn = fminf(w, z);                     // base + m*min(INR,infil)
          float RMO  = fminf(INR, infil);
          float U    = fmaf(-msr, RMO, INR);            // IRUN + SRUN
          float RECn = fmaf(mcr, RMO, relu(SMSn - c.Sc));  // REC + relu(xr)
          p1[sd][i][lane] = make_float2(U, RECn);
          S = SMSn;
        }
        if (k == NCH - 1) fin1[lane] = S;
      }
      __syncthreads();
    }
  } else if (warp == 2) {
    // ---------- stage 2: GW recurrence + RSmax-derived constants ----------
    float G = 0.f;
    for (int e = 0; e < NCH + 4; ++e) {
      const int k = e - 2;
      if (k >= 0 && k < NCH) {
        const int s0 = k & 3, s1 = k % 3, s2 = k & 1;
#pragma unroll
        for (int i = 0; i < CH; i++) {
          float RSmax = p0b[s0][i][lane].x;
          float RECn  = p1[s1][i][lane].y;
          float u   = rsq_ap(RSmax);
          float crs = c.kr * ((u * u) * u);     // kr * RSmax^-1.5
          float krR = c.kr * RSmax;
          float RSov = RSmax - krR;
          float BAS = c.rk * relu(G);
          float GWn = ((G - c.lg) + RECn) - BAS;
          p2[s2][i][lane] = make_float4(BAS, crs, krR, RSov);
          G = GWn;
        }
        if (k == NCH - 1) fin2[lane] = G;
      }
      __syncthreads();
    }
  } else if (warp == 3) {
    // ---------- stage 3: RS recurrence ----------
    float R = 0.f, sqR = 0.f;
    for (int e = 0; e < NCH + 4; ++e) {
      const int k = e - 3;
      if (k >= 0 && k < NCH) {
        const int s0 = k & 3, s1 = k % 3, s2 = k & 1;
#pragma unroll
        for (int i = 0; i < CH; i++) {
          float2 ra = p0b[s0][i][lane];          // RSmax, Area
          float U   = p1[s1][i][lane].x;
          float4 q  = p2[s2][i][lane];           // BAS, crs, krR, RSov
          float inflow = (U + q.x) * ra.y;
          float Rpi = R + inflow;
          float x5  = Rpi - ra.x;
          float t1  = (q.y * sqR) * R;           // kr * R^1.5 / RSmax^1.5
          float RSn_no = fmaf(-t1, R, Rpi);
          float RSn = (x5 > 0.f) ? q.w : RSn_no;
          float sqn = sqrt_ap(RSn);
          float x6  = (RSn + inflow) - ra.x;
          float qno = (q.y * RSn) * (RSn * sqn); // kr*RSn*(RSn/RSmax)^1.5
          p3a[s2][i][lane] = make_float4(x6, q.z, qno, U);
          p3b[s2][i][lane] = make_float2(q.x, 1.f - ra.y);
          if (k == 0 && i == 0) rs0s[lane] = RSn;
          R = RSn; sqR = sqn;
        }
      }
      __syncthreads();
    }
  } else {
    // ---------- stage 4: Q tail + stores ----------
    for (int e = 0; e < NCH + 4; ++e) {
      const int k = e - 4;
      if (k >= 0 && k < NCH) {
        const int s = k & 1;
        float qb0 = 0.f, qb1 = 0.f, qb2 = 0.f;
#pragma unroll
        for (int i = 0; i < CH; i++) {
          float4 a = p3a[s][i][lane];            // x6, krR, qno, U
          float2 b = p3b[s][i][lane];            // BAS, onemA
          float Qor2 = relu(a.x);
          float Qir2 = (a.x > 0.f) ? a.y : a.z;
          float ssum = (Qir2 + Qor2) - c.ls;
          float drarg = fmaf(a.w, b.y, ssum);
          float Q = relu(relu(drarg) + b.x * b.y);
          int ii = i & 3;
          if      (ii == 0) qb0 = Q;
          else if (ii == 1) qb1 = Q;
          else if (ii == 2) qb2 = Q;
          else *reinterpret_cast<float4*>(op + k * CH + i - 3) =
                 make_float4(qb0, qb1, qb2, Q);
        }
      }
      __syncthreads();
    }
    // Q[b,0]: jnp.roll wrap -> SMS1/GW1 = FINAL states; RS = outs[b,0,2]
    float4 f = xin[0];
    op[0] = q_final(f, fin1[lane], fin2[lane], rs0s[lane], c);
  }
}

extern "C" void kernel_launch(void* const* d_in, const int* in_sizes, int n_in,
                              void* d_out, int out_size) {
  const float4* xin = (const float4*)d_in[0];
  int B = out_size / TT;
  int grid = B / 32;
  static int attr_set = 0;
  if (!attr_set) {
    cudaFuncSetAttribute(hirnn_kernel, cudaFuncAttributeMaxDynamicSharedMemorySize, SMEM_TOTAL);
    attr_set = 1;
  }
  hirnn_kernel<<<grid, 160, SMEM_TOTAL>>>(xin,
      (const float*)d_in[1], (const float*)d_in[2], (const float*)d_in[3],
      (const float*)d_in[4], (const float*)d_in[5], (const float*)d_in[6],
      (const float*)d_in[7], (const float*)d_in[8], (const float*)d_in[9],
      (const float*)d_in[10],
      (float*)d_out, B);
}

// round 14
// speedup vs baseline: 1.3426x; 1.3426x over previous
#include <cuda_runtime.h>
#include <cstdint>

#define TT 2048
#define CH 16
#define NCH (TT / CH)      // 128 chunks
#define PAD 33
#define NEP (NCH + 8)      // stage s offset = 2s, depth 4 stages behind

__device__ __forceinline__ float ex2_ap (float x){ float r; asm("ex2.approx.f32 %0, %1;"   : "=f"(r) : "f"(x)); return r; }
__device__ __forceinline__ float rcp_ap (float x){ float r; asm("rcp.approx.f32 %0, %1;"   : "=f"(r) : "f"(x)); return r; }
__device__ __forceinline__ float sqrt_ap(float x){ float r; asm("sqrt.approx.f32 %0, %1;"  : "=f"(r) : "f"(x)); return r; }
__device__ __forceinline__ float rsq_ap (float x){ float r; asm("rsqrt.approx.f32 %0, %1;" : "=f"(r) : "f"(x)); return r; }
__device__ __forceinline__ float clampf(float x, float lo, float hi){ return fminf(fmaxf(x, lo), hi); }
__device__ __forceinline__ float relu(float x){ return fmaxf(x, 0.f); }

// dynamic smem layout (bytes); slots sized for barrier period 2: N >= 2*d_max + 2
#define SZ_P2   (4 * CH * PAD * 16)
#define SZ_P3A  (4 * CH * PAD * 16)
#define SZ_P0A  (4 * CH * PAD * 8)
#define SZ_P0B  (8 * CH * PAD * 8)
#define SZ_P1   (6 * CH * PAD * 8)
#define SZ_P3B  (4 * CH * PAD * 8)
#define OFF_P2   0
#define OFF_P3A  (OFF_P2  + SZ_P2)
#define OFF_P0A  (OFF_P3A + SZ_P3A)
#define OFF_P0B  (OFF_P0A + SZ_P0A)
#define OFF_P1   (OFF_P0B + SZ_P0B)
#define OFF_P3B  (OFF_P1  + SZ_P1)
#define OFF_FIN1 (OFF_P3B + SZ_P3B)
#define OFF_FIN2 (OFF_FIN1 + 128)
#define OFF_RS0  (OFF_FIN2 + 128)
#define SMEM_TOTAL (OFF_RS0 + 128)

struct Consts {
  float insc, Sc, Sinv, kexp, lCc, sub, crak, rk, lg, kr, ls;
};

// Full pass-2 Q for t==0: rolled SMS/GW = FINAL states, RS = outs[b,0,2]
__device__ __forceinline__ float q_final(float4 v, float SMS1r, float GW1r, float RSr, const Consts& c)
{
  float Prec = v.x, PET = v.y, RSmax = v.z, Area = v.w;
  float INTC = fminf(fminf(c.insc, PET), Prec);
  float INR  = Prec - INTC;
  float SMS1c = fmaxf(fminf(SMS1r, c.Sc), 0.f);
  float infil = ex2_ap(fmaf(c.kexp, SMS1c, c.lCc));
  float RMO = fminf(INR, infil);
  float IRUN = INR - RMO;
  float ratio = SMS1c * c.Sinv;
  float SRUN = c.sub * ratio * RMO;
  float BAS = c.rk * relu(GW1r);
  float inflow = (IRUN + SRUN + BAS) * Area;
  float x5 = RSr + inflow - RSmax;
  float Qor = relu(x5);
  float r = relu(RSr) * rcp_ap(RSmax);
  float pw = r * sqrt_ap(r);
  float Qir = (x5 > 0.f) ? (c.kr * RSmax) : (c.kr * RSr * pw);
  float drarg = (SRUN + IRUN) * (1.f - Area) + Qir + Qor - c.ls;
  float DR = relu(drarg);
  float GD = BAS * (1.f - Area);
  return relu(DR + GD);
}

__global__ void __launch_bounds__(160, 1)
hirnn_kernel(const float4* __restrict__ xin_all,
             const float* __restrict__ pINSC, const float* __restrict__ pCOEFF,
             const float* __restrict__ pSQ,   const float* __restrict__ pSMSC,
             const float* __restrict__ pSUB,  const float* __restrict__ pCRAK,
             const float* __restrict__ pRecK, const float* __restrict__ pKr,
             const float* __restrict__ pLG,   const float* __restrict__ pLS,
             float* __restrict__ out, int B)
{
  const int lane = threadIdx.x & 31;
  const int warp = threadIdx.x >> 5;
  const int seq  = blockIdx.x * 32 + lane;

  extern __shared__ unsigned char dyn[];
  typedef float2 P2CH[CH][PAD];
  typedef float4 P4CH[CH][PAD];
  P4CH* p2  = (P4CH*)(dyn + OFF_P2);    // [4]: BAS, crs, krR, RSov
  P4CH* p3a = (P4CH*)(dyn + OFF_P3A);   // [4]: x6, krR, qno, U
  P2CH* p0a = (P2CH*)(dyn + OFF_P0A);   // [4]: INR, POT
  P2CH* p0b = (P2CH*)(dyn + OFF_P0B);   // [8]: RSmax, Area
  P2CH* p1  = (P2CH*)(dyn + OFF_P1);    // [6]: U, RECn
  P2CH* p3b = (P2CH*)(dyn + OFF_P3B);   // [4]: BAS, onemA
  float* fin1 = (float*)(dyn + OFF_FIN1);
  float* fin2 = (float*)(dyn + OFF_FIN2);
  float* rs0s = (float*)(dyn + OFF_RS0);

  Consts c;
  c.insc = clampf(pINSC[0] * 5.f, 0.5f, 5.f);
  float Cc = clampf(pCOEFF[0] * 400.f, 50.f, 400.f);
  float qv = clampf(pSQ[0] * 6.f, 0.f, 6.f);
  c.Sc   = clampf(pSMSC[0] * 500.f, 50.f, 500.f);
  c.Sinv = 1.f / c.Sc;
  c.kexp = -qv * c.Sinv * 1.4426950408889634f;   // Cc*exp(-q*s/S) == exp2(kexp*s + lCc)
  c.lCc  = log2f(Cc);
  c.sub  = clampf(pSUB[0], 0.f, 1.f);
  c.crak = clampf(pCRAK[0], 0.f, 1.f);
  c.rk   = clampf(pRecK[0] * 0.3f, 0.003f, 0.3f);
  c.lg   = clampf(pLG[0] * 0.1f, 0.001f, 0.1f);
  c.kr   = clampf(pKr[0] * 0.1f, 0.01f, 0.1f);
  c.ls   = clampf(pLS[0] * 10.f, 0.01f, 10.f);

  const float4* __restrict__ xin = xin_all + (size_t)seq * TT;
  float* __restrict__ op = out + (size_t)seq * TT;

  if (warp == 0) {
    // ---------- stage 0 (chunk e): load + interception ----------
    float4 bA[CH], bB[CH];
#pragma unroll
    for (int i = 0; i < CH; i++) bA[i] = xin[i];
    for (int e = 0; e < NEP; ++e) {
      if (e < NCH) {
        const int sa = e & 3, sb = e & 7;
        if ((e & 1) == 0) {
          if (e + 1 < NCH) {
#pragma unroll
            for (int i = 0; i < CH; i++) bB[i] = xin[(e + 1) * CH + i];
          }
#pragma unroll
          for (int i = 0; i < CH; i++) {
            float Prec = bA[i].x, PET = bA[i].y;
            float INTC = fminf(fminf(c.insc, PET), Prec);
            p0a[sa][i][lane] = make_float2(Prec - INTC, PET - INTC);
            p0b[sb][i][lane] = make_float2(bA[i].z, bA[i].w);
          }
        } else {
          if (e + 1 < NCH) {
#pragma unroll
            for (int i = 0; i < CH; i++) bA[i] = xin[(e + 1) * CH + i];
          }
#pragma unroll
          for (int i = 0; i < CH; i++) {
            float Prec = bB[i].x, PET = bB[i].y;
            float INTC = fminf(fminf(c.insc, PET), Prec);
            p0a[sa][i][lane] = make_float2(Prec - INTC, PET - INTC);
            p0b[sb][i][lane] = make_float2(bB[i].z, bB[i].w);
          }
        }
      }
      if (e & 1) __syncthreads();
    }
  } else if (warp == 1) {
    // ---------- stage 1 (chunk e-2): SMS recurrence ----------
    float S = 0.f;
    for (int e = 0; e < NEP; ++e) {
      const int k = e - 2;
      if (k >= 0 && k < NCH) {
        const int s0 = k & 3, sd = k % 6;
#pragma unroll
        for (int i = 0; i < CH; i++) {
          float2 io = p0a[s0][i][lane];
          float INR = io.x, POT = io.y;
          float SMS1c = fminf(S, c.Sc);                 // >=0 invariant
          float infil = ex2_ap(fmaf(c.kexp, SMS1c, c.lCc));
          float ratio = SMS1c * c.Sinv;
          float sr  = c.sub  * ratio;
          float cr  = c.crak * ratio;
          float msr = 1.f - sr;
          float m   = msr * (1.f - cr);
          float mcr = cr * msr;
          float ETS  = fminf(POT, 10.f * ratio);
          float base = SMS1c - ETS;
          float w = fmaf(m, INR,   base);
          float z = fmaf(m, infil, base);
          float SMSn = fminf(w, z);                     // base + m*min(INR,infil)
          float RMO  = fminf(INR, infil);
          float U    = fmaf(-msr, RMO, INR);            // IRUN + SRUN
          float RECn = fmaf(mcr, RMO, relu(SMSn - c.Sc));  // REC + relu(xr)
          p1[sd][i][lane] = make_float2(U, RECn);
          S = SMSn;
        }
        if (k == NCH - 1) fin1[lane] = S;
      }
      if (e & 1) __syncthreads();
    }
  } else if (warp == 2) {
    // ---------- stage 2 (chunk e-4): GW recurrence + RSmax consts ----------
    float G = 0.f;
    for (int e = 0; e < NEP; ++e) {
      const int k = e - 4;
      if (k >= 0 && k < NCH) {
        const int s0 = k & 7, s1 = k % 6, s2 = k & 3;
#pragma unroll
        for (int i = 0; i < CH; i++) {
          float RSmax = p0b[s0][i][lane].x;
          float RECn  = p1[s1][i][lane].y;
          float u   = rsq_ap(RSmax);
          float crs = c.kr * ((u * u) * u);     // kr * RSmax^-1.5
          float krR = c.kr * RSmax;
          float RSov = RSmax - krR;
          float BAS = c.rk * relu(G);
          float GWn = ((G - c.lg) + RECn) - BAS;
          p2[s2][i][lane] = make_float4(BAS, crs, krR, RSov);
          G = GWn;
        }
        if (k == NCH - 1) fin2[lane] = G;
      }
      if (e & 1) __syncthreads();
    }
  } else if (warp == 3) {
    // ---------- stage 3 (chunk e-6): RS recurrence ----------
    float R = 0.f, sqR = 0.f;
    for (int e = 0; e < NEP; ++e) {
      const int k = e - 6;
      if (k >= 0 && k < NCH) {
        const int s0 = k & 7, s1 = k % 6, s2 = k & 3;
#pragma unroll
        for (int i = 0; i < CH; i++) {
          float2 ra = p0b[s0][i][lane];          // RSmax, Area
          float U   = p1[s1][i][lane].x;
          float4 q  = p2[s2][i][lane];           // BAS, crs, krR, RSov
          float inflow = (U + q.x) * ra.y;
          float Rpi = R + inflow;
          float x5  = Rpi - ra.x;
          float t1  = (q.y * sqR) * R;           // kr * R^1.5 / RSmax^1.5
          float RSn_no = fmaf(-t1, R, Rpi);
          float RSn = (x5 > 0.f) ? q.w : RSn_no;
          float sqn = sqrt_ap(RSn);
          float x6  = (RSn + inflow) - ra.x;
          float qno = (q.y * RSn) * (RSn * sqn); // kr*RSn*(RSn/RSmax)^1.5
          p3a[s2][i][lane] = make_float4(x6, q.z, qno, U);
          p3b[s2][i][lane] = make_float2(q.x, 1.f - ra.y);
          if (k == 0 && i == 0) rs0s[lane] = RSn;
          R = RSn; sqR = sqn;
        }
      }
      if (e & 1) __syncthreads();
    }
  } else {
    // ---------- stage 4 (chunk e-8): Q tail + stores ----------
    for (int e = 0; e < NEP; ++e) {
      const int k = e - 8;
      if (k >= 0 && k < NCH) {
        const int s = k & 3;
        float qb0 = 0.f, qb1 = 0.f, qb2 = 0.f;
#pragma unroll
        for (int i = 0; i < CH; i++) {
          float4 a = p3a[s][i][lane];            // x6, krR, qno, U
          float2 b = p3b[s][i][lane];            // BAS, onemA
          float Qor2 = relu(a.x);
          float Qir2 = (a.x > 0.f) ? a.y : a.z;
          float ssum = (Qir2 + Qor2) - c.ls;
          float drarg = fmaf(a.w, b.y, ssum);
          float Q = relu(relu(drarg) + b.x * b.y);
          int ii = i & 3;
          if      (ii == 0) qb0 = Q;
          else if (ii == 1) qb1 = Q;
          else if (ii == 2) qb2 = Q;
          else *reinterpret_cast<float4*>(op + k * CH + i - 3) =
                 make_float4(qb0, qb1, qb2, Q);
        }
      }
      if (e & 1) __syncthreads();
    }
    // Q[b,0]: jnp.roll wrap -> SMS1/GW1 = FINAL states; RS = outs[b,0,2]
    float4 f = xin[0];
    op[0] = q_final(f, fin1[lane], fin2[lane], rs0s[lane], c);
  }
}

extern "C" void kernel_launch(void* const* d_in, const int* in_sizes, int n_in,
                              void* d_out, int out_size) {
  const float4* xin = (const float4*)d_in[0];
  int B = out_size / TT;
  int grid = B / 32;
  static int attr_set = 0;
  if (!attr_set) {
    cudaFuncSetAttribute(hirnn_kernel, cudaFuncAttributeMaxDynamicSharedMemorySize, SMEM_TOTAL);
    attr_set = 1;
  }
  hirnn_kernel<<<grid, 160, SMEM_TOTAL>>>(xin,
      (const float*)d_in[1], (const float*)d_in[2], (const float*)d_in[3],
      (const float*)d_in[4], (const float*)d_in[5], (const float*)d_in[6],
      (const float*)d_in[7], (const float*)d_in[8], (const float*)d_in[9],
      (const float*)d_in[10],
      (float*)d_out, B);
}

// round 15
// speedup vs baseline: 1.6517x; 1.2302x over previous
#include <cuda_runtime.h>
#include <cstdint>

#define TT 2048
#define CH 16
#define NCH (TT / CH)      // 128 chunks
#define PAD 33

__device__ __forceinline__ float ex2_ap (float x){ float r; asm("ex2.approx.f32 %0, %1;"   : "=f"(r) : "f"(x)); return r; }
__device__ __forceinline__ float rcp_ap (float x){ float r; asm("rcp.approx.f32 %0, %1;"   : "=f"(r) : "f"(x)); return r; }
__device__ __forceinline__ float sqrt_ap(float x){ float r; asm("sqrt.approx.f32 %0, %1;"  : "=f"(r) : "f"(x)); return r; }
__device__ __forceinline__ float rsq_ap (float x){ float r; asm("rsqrt.approx.f32 %0, %1;" : "=f"(r) : "f"(x)); return r; }
__device__ __forceinline__ float clampf(float x, float lo, float hi){ return fminf(fmaxf(x, lo), hi); }
__device__ __forceinline__ float relu(float x){ return fmaxf(x, 0.f); }

// dynamic smem layout (bytes)
#define SZ_P2   (2 * CH * PAD * 16)
#define SZ_P3A  (2 * CH * PAD * 16)
#define SZ_P0A  (2 * CH * PAD * 8)
#define SZ_P0B  (4 * CH * PAD * 8)
#define SZ_P1   (3 * CH * PAD * 8)
#define SZ_P3B  (2 * CH * PAD * 8)
#define OFF_P2   0
#define OFF_P3A  (OFF_P2  + SZ_P2)
#define OFF_P0A  (OFF_P3A + SZ_P3A)
#define OFF_P0B  (OFF_P0A + SZ_P0A)
#define OFF_P1   (OFF_P0B + SZ_P0B)
#define OFF_P3B  (OFF_P1  + SZ_P1)
#define OFF_FIN1 (OFF_P3B + SZ_P3B)
#define OFF_FIN2 (OFF_FIN1 + 128)
#define OFF_RS0  (OFF_FIN2 + 128)
#define SMEM_TOTAL (OFF_RS0 + 128)

struct Consts {
  float insc, Sc, Sinv, kexp, lCc, sub, crak, rk, lg, kr, ls;
  float tenSinv, a2, b2;
};

// Full pass-2 Q for t==0: rolled SMS/GW = FINAL states, RS = outs[b,0,2]
__device__ __forceinline__ float q_final(float4 v, float SMS1r, float GW1r, float RSr, const Consts& c)
{
  float Prec = v.x, PET = v.y, RSmax = v.z, Area = v.w;
  float INTC = fminf(fminf(c.insc, PET), Prec);
  float INR  = Prec - INTC;
  float SMS1c = fmaxf(fminf(SMS1r, c.Sc), 0.f);
  float infil = ex2_ap(fmaf(c.kexp, SMS1c, c.lCc));
  float RMO = fminf(INR, infil);
  float IRUN = INR - RMO;
  float ratio = SMS1c * c.Sinv;
  float SRUN = c.sub * ratio * RMO;
  float BAS = c.rk * relu(GW1r);
  float inflow = (IRUN + SRUN + BAS) * Area;
  float x5 = RSr + inflow - RSmax;
  float Qor = relu(x5);
  float r = relu(RSr) * rcp_ap(RSmax);
  float pw = r * sqrt_ap(r);
  float Qir = (x5 > 0.f) ? (c.kr * RSmax) : (c.kr * RSr * pw);
  float drarg = (SRUN + IRUN) * (1.f - Area) + Qir + Qor - c.ls;
  float DR = relu(drarg);
  float GD = BAS * (1.f - Area);
  return relu(DR + GD);
}

__global__ void __launch_bounds__(160, 1)
hirnn_kernel(const float4* __restrict__ xin_all,
             const float* __restrict__ pINSC, const float* __restrict__ pCOEFF,
             const float* __restrict__ pSQ,   const float* __restrict__ pSMSC,
             const float* __restrict__ pSUB,  const float* __restrict__ pCRAK,
             const float* __restrict__ pRecK, const float* __restrict__ pKr,
             const float* __restrict__ pLG,   const float* __restrict__ pLS,
             float* __restrict__ out, int B)
{
  const int lane = threadIdx.x & 31;
  const int warp = threadIdx.x >> 5;
  const int seq  = blockIdx.x * 32 + lane;

  extern __shared__ unsigned char dyn[];
  typedef float2 P2CH[CH][PAD];
  typedef float4 P4CH[CH][PAD];
  P4CH* p2  = (P4CH*)(dyn + OFF_P2);    // [2]: BAS, crs, krR, RSov
  P4CH* p3a = (P4CH*)(dyn + OFF_P3A);   // [2]: x6, krR, qno, U
  P2CH* p0a = (P2CH*)(dyn + OFF_P0A);   // [2]: INR, POT
  P2CH* p0b = (P2CH*)(dyn + OFF_P0B);   // [4]: RSmax, Area
  P2CH* p1  = (P2CH*)(dyn + OFF_P1);    // [3]: U, RECn
  P2CH* p3b = (P2CH*)(dyn + OFF_P3B);   // [2]: BAS, onemA
  float* fin1 = (float*)(dyn + OFF_FIN1);
  float* fin2 = (float*)(dyn + OFF_FIN2);
  float* rs0s = (float*)(dyn + OFF_RS0);

  Consts c;
  c.insc = clampf(pINSC[0] * 5.f, 0.5f, 5.f);
  float Cc = clampf(pCOEFF[0] * 400.f, 50.f, 400.f);
  float qv = clampf(pSQ[0] * 6.f, 0.f, 6.f);
  c.Sc   = clampf(pSMSC[0] * 500.f, 50.f, 500.f);
  c.Sinv = 1.f / c.Sc;
  c.kexp = -qv * c.Sinv * 1.4426950408889634f;   // Cc*exp(-q*s/S) == exp2(kexp*s + lCc)
  c.lCc  = log2f(Cc);
  c.sub  = clampf(pSUB[0], 0.f, 1.f);
  c.crak = clampf(pCRAK[0], 0.f, 1.f);
  c.rk   = clampf(pRecK[0] * 0.3f, 0.003f, 0.3f);
  c.lg   = clampf(pLG[0] * 0.1f, 0.001f, 0.1f);
  c.kr   = clampf(pKr[0] * 0.1f, 0.01f, 0.1f);
  c.ls   = clampf(pLS[0] * 10.f, 0.01f, 10.f);
  c.tenSinv = 10.f * c.Sinv;
  c.a2 = c.sub + c.crak;
  c.b2 = c.sub * c.crak;

  const float4* __restrict__ xin = xin_all + (size_t)seq * TT;
  float* __restrict__ op = out + (size_t)seq * TT;

  if (warp == 0) {
    // ---------- stage 0: load + interception (full-chunk double buffer) ----------
    float4 bA[CH], bB[CH];
#pragma unroll
    for (int i = 0; i < CH; i++) bA[i] = xin[i];
    for (int e = 0; e < NCH + 4; ++e) {
      if (e < NCH) {
        const int s1 = e & 1, s3 = e & 3;
        if ((e & 1) == 0) {
          if (e + 1 < NCH) {
#pragma unroll
            for (int i = 0; i < CH; i++) bB[i] = xin[(e + 1) * CH + i];
          }
#pragma unroll
          for (int i = 0; i < CH; i++) {
            float Prec = bA[i].x, PET = bA[i].y;
            float INTC = fminf(fminf(c.insc, PET), Prec);
            p0a[s1][i][lane] = make_float2(Prec - INTC, PET - INTC);
            p0b[s3][i][lane] = make_float2(bA[i].z, bA[i].w);
          }
        } else {
          if (e + 1 < NCH) {
#pragma unroll
            for (int i = 0; i < CH; i++) bA[i] = xin[(e + 1) * CH + i];
          }
#pragma unroll
          for (int i = 0; i < CH; i++) {
            float Prec = bB[i].x, PET = bB[i].y;
            float INTC = fminf(fminf(c.insc, PET), Prec);
            p0a[s1][i][lane] = make_float2(Prec - INTC, PET - INTC);
            p0b[s3][i][lane] = make_float2(bB[i].z, bB[i].w);
          }
        }
      }
      __syncthreads();
    }
  } else if (warp == 1) {
    // ---------- stage 1: SMS recurrence (batched LDS prefetch) ----------
    float S = 0.f;
    for (int e = 0; e < NCH + 4; ++e) {
      const int k = e - 1;
      if (k >= 0 && k < NCH) {
        const int s0 = k & 1, sd = k % 3;
        float2 io[CH];
#pragma unroll
        for (int i = 0; i < CH; i++) io[i] = p0a[s0][i][lane];
#pragma unroll
        for (int i = 0; i < CH; i++) {
          float INR = io[i].x, POT = io[i].y;
          float SMS1c = fminf(S, c.Sc);                 // >=0 invariant
          float infil = ex2_ap(fmaf(c.kexp, SMS1c, c.lCc));
          float ratio = SMS1c * c.Sinv;
          float ETS  = fminf(POT, SMS1c * c.tenSinv);
          float base = SMS1c - ETS;
          float m = fmaf(fmaf(c.b2, ratio, -c.a2), ratio, 1.f);  // (1-sr)(1-cr)
          float w = fmaf(m, INR,   base);
          float z = fmaf(m, infil, base);
          float SMSn = fminf(w, z);                     // base + m*min(INR,infil)
          float RMO  = fminf(INR, infil);
          float msr  = fmaf(-c.sub, ratio, 1.f);
          float mcr  = (c.crak * ratio) * msr;
          float U    = fmaf(-msr, RMO, INR);            // IRUN + SRUN
          float RECn = fmaf(mcr, RMO, relu(SMSn - c.Sc));  // REC + relu(xr)
          p1[sd][i][lane] = make_float2(U, RECn);
          S = SMSn;
        }
        if (k == NCH - 1) fin1[lane] = S;
      }
      __syncthreads();
    }
  } else if (warp == 2) {
    // ---------- stage 2: GW recurrence + RSmax consts (batched LDS prefetch) ----------
    float G = 0.f;
    for (int e = 0; e < NCH + 4; ++e) {
      const int k = e - 2;
      if (k >= 0 && k < NCH) {
        const int s0 = k & 3, s1 = k % 3, s2 = k & 1;
        float rms[CH], rcn[CH];
#pragma unroll
        for (int i = 0; i < CH; i++) rms[i] = p0b[s0][i][lane].x;
#pragma unroll
        for (int i = 0; i < CH; i++) rcn[i] = p1[s1][i][lane].y;
#pragma unroll
        for (int i = 0; i < CH; i++) {
          float RSmax = rms[i];
          float u   = rsq_ap(RSmax);
          float crs = c.kr * ((u * u) * u);     // kr * RSmax^-1.5
          float krR = c.kr * RSmax;
          float RSov = RSmax - krR;
          float BAS = c.rk * relu(G);
          float GWn = ((G - c.lg) + rcn[i]) - BAS;
          p2[s2][i][lane] = make_float4(BAS, crs, krR, RSov);
          G = GWn;
        }
        if (k == NCH - 1) fin2[lane] = G;
      }
      __syncthreads();
    }
  } else if (warp == 3) {
    // ---------- stage 3: RS recurrence (prefetch in 8-step halves) ----------
    float R = 0.f, sqR = 0.f;
    for (int e = 0; e < NCH + 4; ++e) {
      const int k = e - 3;
      if (k >= 0 && k < NCH) {
        const int s0 = k & 3, s1 = k % 3, s2 = k & 1;
#pragma unroll
        for (int h = 0; h < 2; ++h) {
          float2 ra[8]; float Ux[8]; float4 q[8];
#pragma unroll
          for (int j = 0; j < 8; ++j) {
            int idx = h * 8 + j;
            ra[j] = p0b[s0][idx][lane];
            Ux[j] = p1[s1][idx][lane].x;
            q[j]  = p2[s2][idx][lane];
          }
#pragma unroll
          for (int j = 0; j < 8; ++j) {
            int idx = h * 8 + j;
            float inflow = (Ux[j] + q[j].x) * ra[j].y;
            float Rpi = R + inflow;
            float x5  = Rpi - ra[j].x;
            float t1  = (q[j].y * sqR) * R;        // kr * R^1.5 / RSmax^1.5
            float RSn_no = fmaf(-t1, R, Rpi);
            float RSn = (x5 > 0.f) ? q[j].w : RSn_no;
            float sqn = sqrt_ap(RSn);
            float x6  = (RSn + inflow) - ra[j].x;
            float qno = (q[j].y * RSn) * (RSn * sqn);  // kr*RSn*(RSn/RSmax)^1.5
            p3a[s2][idx][lane] = make_float4(x6, q[j].z, qno, Ux[j]);
            p3b[s2][idx][lane] = make_float2(q[j].x, 1.f - ra[j].y);
            if (k == 0 && idx == 0) rs0s[lane] = RSn;
            R = RSn; sqR = sqn;
          }
        }
      }
      __syncthreads();
    }
  } else {
    // ---------- stage 4: Q tail + stores (prefetch in 8-step halves) ----------
    for (int e = 0; e < NCH + 4; ++e) {
      const int k = e - 4;
      if (k >= 0 && k < NCH) {
        const int s = k & 1;
#pragma unroll
        for (int h = 0; h < 2; ++h) {
          float4 a[8]; float2 b[8];
#pragma unroll
          for (int j = 0; j < 8; ++j) {
            int idx = h * 8 + j;
            a[j] = p3a[s][idx][lane];
            b[j] = p3b[s][idx][lane];
          }
          float qb0 = 0.f, qb1 = 0.f, qb2 = 0.f;
#pragma unroll
          for (int j = 0; j < 8; ++j) {
            float Qor2 = relu(a[j].x);
            float Qir2 = (a[j].x > 0.f) ? a[j].y : a[j].z;
            float ssum = (Qir2 + Qor2) - c.ls;
            float drarg = fmaf(a[j].w, b[j].y, ssum);
            float Q = relu(relu(drarg) + b[j].x * b[j].y);
            int ii = j & 3;
            if      (ii == 0) qb0 = Q;
            else if (ii == 1) qb1 = Q;
            else if (ii == 2) qb2 = Q;
            else *reinterpret_cast<float4*>(op + k * CH + h * 8 + j - 3) =
                   make_float4(qb0, qb1, qb2, Q);
          }
        }
      }
      __syncthreads();
    }
    // Q[b,0]: jnp.roll wrap -> SMS1/GW1 = FINAL states; RS = outs[b,0,2]
    float4 f = xin[0];
    op[0] = q_final(f, fin1[lane], fin2[lane], rs0s[lane], c);
  }
}

extern "C" void kernel_launch(void* const* d_in, const int* in_sizes, int n_in,
                              void* d_out, int out_size) {
  const float4* xin = (const float4*)d_in[0];
  int B = out_size / TT;
  int grid = B / 32;
  static int attr_set = 0;
  if (!attr_set) {
    cudaFuncSetAttribute(hirnn_kernel, cudaFuncAttributeMaxDynamicSharedMemorySize, SMEM_TOTAL);
    attr_set = 1;
  }
  hirnn_kernel<<<grid, 160, SMEM_TOTAL>>>(xin,
      (const float*)d_in[1], (const float*)d_in[2], (const float*)d_in[3],
      (const float*)d_in[4], (const float*)d_in[5], (const float*)d_in[6],
      (const float*)d_in[7], (const float*)d_in[8], (const float*)d_in[9],
      (const float*)d_in[10],
      (float*)d_out, B);
}

// round 16
// speedup vs baseline: 1.6910x; 1.0238x over previous
#include <cuda_runtime.h>
#include <cstdint>

#define TT 2048
#define CH 16
#define NCH (TT / CH)      // 128 chunks
#define PAD 33

__device__ __forceinline__ float ex2_ap (float x){ float r; asm("ex2.approx.f32 %0, %1;"   : "=f"(r) : "f"(x)); return r; }
__device__ __forceinline__ float rcp_ap (float x){ float r; asm("rcp.approx.f32 %0, %1;"   : "=f"(r) : "f"(x)); return r; }
__device__ __forceinline__ float sqrt_ap(float x){ float r; asm("sqrt.approx.f32 %0, %1;"  : "=f"(r) : "f"(x)); return r; }
__device__ __forceinline__ float rsq_ap (float x){ float r; asm("rsqrt.approx.f32 %0, %1;" : "=f"(r) : "f"(x)); return r; }
__device__ __forceinline__ float clampf(float x, float lo, float hi){ return fminf(fmaxf(x, lo), hi); }
__device__ __forceinline__ float relu(float x){ return fmaxf(x, 0.f); }

// dynamic smem layout (bytes)
#define F2PLANE (CH * PAD * 8)
#define F4PLANE (CH * PAD * 16)
#define OFF_P1   0                          // f4 x3 : SMS1c, infil, xrr
#define OFF_P2A  (OFF_P1  + 3 * F4PLANE)    // f4 x4 : BAS, crs, krR, RSov
#define OFF_P0A  (OFF_P2A + 4 * F4PLANE)    // f2 x4 : INR, POT
#define OFF_P0B  (OFF_P0A + 4 * F2PLANE)    // f2 x4 : RSmax, Area
#define OFF_P2B  (OFF_P0B + 4 * F2PLANE)    // f2 x4 : U, onemA
#define OFF_P3   (OFF_P2B + 4 * F2PLANE)    // f2 x2 : RSn, x6
#define OFF_FIN1 (OFF_P3  + 2 * F2PLANE)
#define OFF_FIN2 (OFF_FIN1 + 128)
#define OFF_RS0  (OFF_FIN2 + 128)
#define SMEM_TOTAL (OFF_RS0 + 128)

struct Consts {
  float insc, Sc, Sinv, kexp, lCc, sub, crak, rk, lg, kr, ls;
  float tenSinv, a2, b2;
};

// Full pass-2 Q for t==0: rolled SMS/GW = FINAL states, RS = outs[b,0,2]
__device__ __forceinline__ float q_final(float4 v, float SMS1r, float GW1r, float RSr, const Consts& c)
{
  float Prec = v.x, PET = v.y, RSmax = v.z, Area = v.w;
  float INTC = fminf(fminf(c.insc, PET), Prec);
  float INR  = Prec - INTC;
  float SMS1c = fmaxf(fminf(SMS1r, c.Sc), 0.f);
  float infil = ex2_ap(fmaf(c.kexp, SMS1c, c.lCc));
  float RMO = fminf(INR, infil);
  float IRUN = INR - RMO;
  float ratio = SMS1c * c.Sinv;
  float SRUN = c.sub * ratio * RMO;
  float BAS = c.rk * relu(GW1r);
  float inflow = (IRUN + SRUN + BAS) * Area;
  float x5 = RSr + inflow - RSmax;
  float Qor = relu(x5);
  float r = relu(RSr) * rcp_ap(RSmax);
  float pw = r * sqrt_ap(r);
  float Qir = (x5 > 0.f) ? (c.kr * RSmax) : (c.kr * RSr * pw);
  float drarg = (SRUN + IRUN) * (1.f - Area) + Qir + Qor - c.ls;
  float DR = relu(drarg);
  float GD = BAS * (1.f - Area);
  return relu(DR + GD);
}

__global__ void __launch_bounds__(160, 1)
hirnn_kernel(const float4* __restrict__ xin_all,
             const float* __restrict__ pINSC, const float* __restrict__ pCOEFF,
             const float* __restrict__ pSQ,   const float* __restrict__ pSMSC,
             const float* __restrict__ pSUB,  const float* __restrict__ pCRAK,
             const float* __restrict__ pRecK, const float* __restrict__ pKr,
             const float* __restrict__ pLG,   const float* __restrict__ pLS,
             float* __restrict__ out, int B)
{
  const int lane = threadIdx.x & 31;
  const int warp = threadIdx.x >> 5;
  const int seq  = blockIdx.x * 32 + lane;

  extern __shared__ unsigned char dyn[];
  typedef float2 P2CH[CH][PAD];
  typedef float4 P4CH[CH][PAD];
  P4CH* p1  = (P4CH*)(dyn + OFF_P1);    // [3]: SMS1c, infil, xrr
  P4CH* p2a = (P4CH*)(dyn + OFF_P2A);   // [4]: BAS, crs, krR, RSov
  P2CH* p0a = (P2CH*)(dyn + OFF_P0A);   // [4]: INR, POT
  P2CH* p0b = (P2CH*)(dyn + OFF_P0B);   // [4]: RSmax, Area
  P2CH* p2b = (P2CH*)(dyn + OFF_P2B);   // [4]: U, onemA
  P2CH* p3  = (P2CH*)(dyn + OFF_P3);    // [2]: RSn, x6
  float* fin1 = (float*)(dyn + OFF_FIN1);
  float* fin2 = (float*)(dyn + OFF_FIN2);
  float* rs0s = (float*)(dyn + OFF_RS0);

  Consts c;
  c.insc = clampf(pINSC[0] * 5.f, 0.5f, 5.f);
  float Cc = clampf(pCOEFF[0] * 400.f, 50.f, 400.f);
  float qv = clampf(pSQ[0] * 6.f, 0.f, 6.f);
  c.Sc   = clampf(pSMSC[0] * 500.f, 50.f, 500.f);
  c.Sinv = 1.f / c.Sc;
  c.kexp = -qv * c.Sinv * 1.4426950408889634f;   // Cc*exp(-q*s/S) == exp2(kexp*s + lCc)
  c.lCc  = log2f(Cc);
  c.sub  = clampf(pSUB[0], 0.f, 1.f);
  c.crak = clampf(pCRAK[0], 0.f, 1.f);
  c.rk   = clampf(pRecK[0] * 0.3f, 0.003f, 0.3f);
  c.lg   = clampf(pLG[0] * 0.1f, 0.001f, 0.1f);
  c.kr   = clampf(pKr[0] * 0.1f, 0.01f, 0.1f);
  c.ls   = clampf(pLS[0] * 10.f, 0.01f, 10.f);
  c.tenSinv = 10.f * c.Sinv;
  c.a2 = c.sub + c.crak;
  c.b2 = c.sub * c.crak;

  const float4* __restrict__ xin = xin_all + (size_t)seq * TT;
  float* __restrict__ op = out + (size_t)seq * TT;

  if (warp == 0) {
    // ---------- stage 0 (chunk e): load + interception ----------
    float4 bA[CH], bB[CH];
#pragma unroll
    for (int i = 0; i < CH; i++) bA[i] = xin[i];
    for (int e = 0; e < NCH + 4; ++e) {
      if (e < NCH) {
        const int sa = e & 3, sb = e & 3;
        if ((e & 1) == 0) {
          if (e + 1 < NCH) {
#pragma unroll
            for (int i = 0; i < CH; i++) bB[i] = xin[(e + 1) * CH + i];
          }
#pragma unroll
          for (int i = 0; i < CH; i++) {
            float Prec = bA[i].x, PET = bA[i].y;
            float INTC = fminf(fminf(c.insc, PET), Prec);
            p0a[sa][i][lane] = make_float2(Prec - INTC, PET - INTC);
            p0b[sb][i][lane] = make_float2(bA[i].z, bA[i].w);
          }
        } else {
          if (e + 1 < NCH) {
#pragma unroll
            for (int i = 0; i < CH; i++) bA[i] = xin[(e + 1) * CH + i];
          }
#pragma unroll
          for (int i = 0; i < CH; i++) {
            float Prec = bB[i].x, PET = bB[i].y;
            float INTC = fminf(fminf(c.insc, PET), Prec);
            p0a[sa][i][lane] = make_float2(Prec - INTC, PET - INTC);
            p0b[sb][i][lane] = make_float2(bB[i].z, bB[i].w);
          }
        }
      }
      __syncthreads();
    }
  } else if (warp == 1) {
    // ---------- stage 1 (chunk e-1): SMS recurrence only ----------
    float S = 0.f;
    for (int e = 0; e < NCH + 4; ++e) {
      const int k = e - 1;
      if (k >= 0 && k < NCH) {
        const int s0 = k & 3, sd = k % 3;
        float2 io[CH];
#pragma unroll
        for (int i = 0; i < CH; i++) io[i] = p0a[s0][i][lane];
#pragma unroll
        for (int i = 0; i < CH; i++) {
          float INR = io[i].x, POT = io[i].y;
          float SMS1c = fminf(S, c.Sc);                 // >=0 invariant
          float infil = ex2_ap(fmaf(c.kexp, SMS1c, c.lCc));
          float ratio = SMS1c * c.Sinv;
          float ETS  = fminf(POT, SMS1c * c.tenSinv);
          float base = SMS1c - ETS;
          float m = fmaf(fmaf(c.b2, ratio, -c.a2), ratio, 1.f);  // (1-sr)(1-cr)
          float w = fmaf(m, INR,   base);
          float z = fmaf(m, infil, base);
          float SMSn = fminf(w, z);                     // base + m*min(INR,infil)
          float xrr  = relu(SMSn - c.Sc);
          p1[sd][i][lane] = make_float4(SMS1c, infil, xrr, 0.f);
          S = SMSn;
        }
        if (k == NCH - 1) fin1[lane] = S;
      }
      __syncthreads();
    }
  } else if (warp == 2) {
    // ---------- stage 2 (chunk e-2): U/RECn + GW recurrence + RSmax consts ----------
    float G = 0.f;
    for (int e = 0; e < NCH + 4; ++e) {
      const int k = e - 2;
      if (k >= 0 && k < NCH) {
        const int s0 = k & 3, s1 = k % 3, s2 = k & 3;
#pragma unroll
        for (int h = 0; h < 2; ++h) {
          float2 io[8], rb[8]; float4 sp[8];
#pragma unroll
          for (int j = 0; j < 8; ++j) {
            int idx = h * 8 + j;
            io[j] = p0a[s0][idx][lane];
            rb[j] = p0b[s0][idx][lane];
            sp[j] = p1[s1][idx][lane];
          }
#pragma unroll
          for (int j = 0; j < 8; ++j) {
            int idx = h * 8 + j;
            float INR = io[j].x;
            float SMS1c = sp[j].x, infil = sp[j].y, xrr = sp[j].z;
            float RSmax = rb[j].x, Area = rb[j].y;
            float ratio = SMS1c * c.Sinv;
            float msr  = fmaf(-c.sub, ratio, 1.f);
            float mcr  = (c.crak * ratio) * msr;
            float RMO  = fminf(INR, infil);
            float U    = fmaf(-msr, RMO, INR);          // IRUN + SRUN
            float RECn = fmaf(mcr, RMO, xrr);           // REC + relu(xr)
            float BAS  = c.rk * relu(G);
            float GWn  = ((G - c.lg) + RECn) - BAS;
            float u    = rsq_ap(RSmax);
            float crs  = c.kr * ((u * u) * u);          // kr * RSmax^-1.5
            float krR  = c.kr * RSmax;
            float RSov = RSmax - krR;
            p2a[s2][idx][lane] = make_float4(BAS, crs, krR, RSov);
            p2b[s2][idx][lane] = make_float2(U, 1.f - Area);
            G = GWn;
          }
        }
        if (k == NCH - 1) fin2[lane] = G;
      }
      __syncthreads();
    }
  } else if (warp == 3) {
    // ---------- stage 3 (chunk e-3): bare RS recurrence ----------
    float R = 0.f, sqR = 0.f;
    for (int e = 0; e < NCH + 4; ++e) {
      const int k = e - 3;
      if (k >= 0 && k < NCH) {
        const int s0 = k & 3, s2 = k & 3, sd = k & 1;
#pragma unroll
        for (int h = 0; h < 2; ++h) {
          float2 rb[8], qb[8]; float4 qa[8];
#pragma unroll
          for (int j = 0; j < 8; ++j) {
            int idx = h * 8 + j;
            rb[j] = p0b[s0][idx][lane];
            qa[j] = p2a[s2][idx][lane];
            qb[j] = p2b[s2][idx][lane];
          }
#pragma unroll
          for (int j = 0; j < 8; ++j) {
            int idx = h * 8 + j;
            float RSmax = rb[j].x, Area = rb[j].y;
            float U = qb[j].x, BAS = qa[j].x;
            float inflow = (U + BAS) * Area;
            float Rpi = R + inflow;
            float x5  = Rpi - RSmax;
            float t1  = (qa[j].y * sqR) * R;            // kr * R^1.5 / RSmax^1.5
            float RSn_no = fmaf(-t1, R, Rpi);
            float RSn = (x5 > 0.f) ? qa[j].w : RSn_no;
            float sqn = sqrt_ap(RSn);
            float x6  = (RSn + inflow) - RSmax;
            p3[sd][idx][lane] = make_float2(RSn, x6);
            if (k == 0 && idx == 0) rs0s[lane] = RSn;
            R = RSn; sqR = sqn;
          }
        }
      }
      __syncthreads();
    }
  } else {
    // ---------- stage 4 (chunk e-4): full Q tail + stores ----------
    for (int e = 0; e < NCH + 4; ++e) {
      const int k = e - 4;
      if (k >= 0 && k < NCH) {
        const int s2 = k & 3, s3 = k & 1;
#pragma unroll
        for (int h = 0; h < 2; ++h) {
          float2 r3[8], qb[8]; float4 qa[8];
#pragma unroll
          for (int j = 0; j < 8; ++j) {
            int idx = h * 8 + j;
            r3[j] = p3[s3][idx][lane];
            qa[j] = p2a[s2][idx][lane];
            qb[j] = p2b[s2][idx][lane];
          }
          float qb0 = 0.f, qb1 = 0.f, qb2 = 0.f;
#pragma unroll
          for (int j = 0; j < 8; ++j) {
            float RSn = r3[j].x, x6 = r3[j].y;
            float BAS = qa[j].x, crs = qa[j].y, krR = qa[j].z;
            float U = qb[j].x, onemA = qb[j].y;
            float sqn = sqrt_ap(RSn);
            float Qor2 = relu(x6);
            float qno = (crs * RSn) * (RSn * sqn);      // kr*RSn*(RSn/RSmax)^1.5
            float Qir2 = (x6 > 0.f) ? krR : qno;
            float ssum = (Qir2 + Qor2) - c.ls;
            float drarg = fmaf(U, onemA, ssum);
            float Q = relu(relu(drarg) + BAS * onemA);
            int ii = j & 3;
            if      (ii == 0) qb0 = Q;
            else if (ii == 1) qb1 = Q;
            else if (ii == 2) qb2 = Q;
            else *reinterpret_cast<float4*>(op + k * CH + h * 8 + j - 3) =
                   make_float4(qb0, qb1, qb2, Q);
          }
        }
      }
      __syncthreads();
    }
    // Q[b,0]: jnp.roll wrap -> SMS1/GW1 = FINAL states; RS = outs[b,0,2]
    float4 f = xin[0];
    op[0] = q_final(f, fin1[lane], fin2[lane], rs0s[lane], c);
  }
}

extern "C" void kernel_launch(void* const* d_in, const int* in_sizes, int n_in,
                              void* d_out, int out_size) {
  const float4* xin = (const float4*)d_in[0];
  int B = out_size / TT;
  int grid = B / 32;
  static int attr_set = 0;
  if (!attr_set) {
    cudaFuncSetAttribute(hirnn_kernel, cudaFuncAttributeMaxDynamicSharedMemorySize, SMEM_TOTAL);
    attr_set = 1;
  }
  hirnn_kernel<<<grid, 160, SMEM_TOTAL>>>(xin,
      (const float*)d_in[1], (const float*)d_in[2], (const float*)d_in[3],
      (const float*)d_in[4], (const float*)d_in[5], (const float*)d_in[6],
      (const float*)d_in[7], (const float*)d_in[8], (const float*)d_in[9],
      (const float*)d_in[10],
      (float*)d_out, B);
}